// round 12
// baseline (speedup 1.0000x reference)
#include <cuda_runtime.h>
#include <cuda_bf16.h>
#include <math.h>

#define NN 50000
#define EE 800000
#define DD 64
#define CAP 64               // bucket capacity per node (deg~Pois(16); P(>=64)~1e-20)
#define THREADS 256

// ---------------- scratch (device globals; no allocation allowed) ----------
__device__ int   g_cnt[NN];                     // re-zeroed in phase D each run
__device__ __align__(16) int g_buck[NN * CAP];  // src indices, bucketed by dst
__device__ float g_dinv[NN];
__device__ __align__(16) float g_h0[NN * DD];   // x @ W1 (unscaled)
__device__ float g_q[NN];                       // dinv * (relu(.)@W2)

// software grid barrier (persistent across replays; self-resetting)
__device__ volatile unsigned g_bar_gen;
__device__ unsigned          g_bar_cnt;

__device__ __forceinline__ void grid_sync() {
    __threadfence();
    __syncthreads();
    if (threadIdx.x == 0) {
        unsigned g = g_bar_gen;
        if (atomicAdd(&g_bar_cnt, 1u) == gridDim.x - 1) {
            g_bar_cnt = 0;               // safe: all blocks have arrived
            __threadfence();
            g_bar_gen = g + 1;           // release
        } else {
            while (g_bar_gen == g) { __nanosleep(40); }
        }
    }
    __syncthreads();
}

// ---------------- the one kernel -------------------------------------------
__global__ void __launch_bounds__(THREADS, 6)
k_fused(const float* __restrict__ x,
        const int4*  __restrict__ src4,
        const int4*  __restrict__ dst4,
        const float* __restrict__ W1,
        const float* __restrict__ b1,
        const float* __restrict__ W2,
        const float* __restrict__ b2,
        float*       __restrict__ out)
{
    __shared__ float sW[DD * DD];          // 16 KB (only smem in the kernel)
    const int tid = threadIdx.x;
    const int bid = blockIdx.x;
    const int nb  = gridDim.x;

    // ===== Phase A: block-split  countplace (80%)  ||  gemm (20%) ==========
    const int gemm_blocks = nb / 5;
    if (bid >= gemm_blocks) {
        const int cpb  = nb - gemm_blocks;
        const int cbid = bid - gemm_blocks;
        for (int i = cbid * THREADS + tid; i < EE / 4; i += cpb * THREADS) {
            int4 s = src4[i];
            int4 d = dst4[i];
            g_buck[d.x * CAP + atomicAdd(&g_cnt[d.x], 1)] = s.x;
            g_buck[d.y * CAP + atomicAdd(&g_cnt[d.y], 1)] = s.y;
            g_buck[d.z * CAP + atomicAdd(&g_cnt[d.z], 1)] = s.z;
            g_buck[d.w * CAP + atomicAdd(&g_cnt[d.w], 1)] = s.w;
        }
    } else {
        // load W1 to smem once per block
        for (int j = tid; j < DD * DD / 4; j += THREADS)
            ((float4*)sW)[j] = ((const float4*)W1)[j];
        __syncthreads();

        // 4 nodes per block-iteration; thread t -> node (t>>6), dim (t&63).
        // x row values broadcast within each 64-thread group (L1-served).
        const int d = tid & 63;
        const int nsub = tid >> 6;
        for (int n4 = bid; n4 < (NN + 3) / 4; n4 += gemm_blocks) {
            int node = n4 * 4 + nsub;
            if (node < NN) {
                const float* xr = x + (size_t)node * DD;
                float sum = 0.f;
                #pragma unroll 16
                for (int k = 0; k < DD; k++)
                    sum = fmaf(__ldg(&xr[k]), sW[k * DD + d], sum);
                g_h0[(size_t)node * DD + d] = sum;
            }
        }
    }
    grid_sync();

    // ===== Phase B: dinv ====================================================
    for (int i = bid * THREADS + tid; i < NN; i += nb * THREADS)
        g_dinv[i] = rsqrtf((float)(g_cnt[i] + 1));   // +1 self-loop
    grid_sync();

    // ===== Phase C: agg1 + bias + relu + W2 projection (R8 config) ==========
    {
        const int l = tid & 15;
        const int hw0 = bid * (THREADS / 16) + (tid >> 4);
        const int hws = nb * (THREADS / 16);
        for (int node = hw0; node < NN; node += hws) {
            const float di  = g_dinv[node];
            const int   deg = g_cnt[node];
            const int   base = node * CAP;

            float4 v0 = ((const float4*)(g_h0 + (size_t)node * DD))[l];   // self
            float ax = di * v0.x, ay = di * v0.y, az = di * v0.z, aw = di * v0.w;

            int j = 0;
            for (; j + 4 <= deg; j += 4) {
                int c0 = __ldg(&g_buck[base + j]);
                int c1 = __ldg(&g_buck[base + j + 1]);
                int c2 = __ldg(&g_buck[base + j + 2]);
                int c3 = __ldg(&g_buck[base + j + 3]);
                float w0 = __ldg(&g_dinv[c0]);
                float w1 = __ldg(&g_dinv[c1]);
                float w2 = __ldg(&g_dinv[c2]);
                float w3 = __ldg(&g_dinv[c3]);
                float4 a = ((const float4*)(g_h0 + (size_t)c0 * DD))[l];
                float4 b = ((const float4*)(g_h0 + (size_t)c1 * DD))[l];
                float4 c = ((const float4*)(g_h0 + (size_t)c2 * DD))[l];
                float4 d = ((const float4*)(g_h0 + (size_t)c3 * DD))[l];
                ax = fmaf(w0, a.x, fmaf(w1, b.x, fmaf(w2, c.x, fmaf(w3, d.x, ax))));
                ay = fmaf(w0, a.y, fmaf(w1, b.y, fmaf(w2, c.y, fmaf(w3, d.y, ay))));
                az = fmaf(w0, a.z, fmaf(w1, b.z, fmaf(w2, c.z, fmaf(w3, d.z, az))));
                aw = fmaf(w0, a.w, fmaf(w1, b.w, fmaf(w2, c.w, fmaf(w3, d.w, aw))));
            }
            for (; j < deg; j++) {
                int c0 = __ldg(&g_buck[base + j]);
                float w0 = __ldg(&g_dinv[c0]);
                float4 a = ((const float4*)(g_h0 + (size_t)c0 * DD))[l];
                ax = fmaf(w0, a.x, ax); ay = fmaf(w0, a.y, ay);
                az = fmaf(w0, a.z, az); aw = fmaf(w0, a.w, aw);
            }

            float4 bb = ((const float4*)b1)[l];
            float4 ww = ((const float4*)W2)[l];
            float part = fmaxf(ax * di + bb.x, 0.f) * ww.x
                       + fmaxf(ay * di + bb.y, 0.f) * ww.y
                       + fmaxf(az * di + bb.z, 0.f) * ww.z
                       + fmaxf(aw * di + bb.w, 0.f) * ww.w;
            #pragma unroll
            for (int o = 8; o; o >>= 1)
                part += __shfl_down_sync(0xffffffffu, part, o, 16);
            if (l == 0) g_q[node] = di * part;
        }
    }
    grid_sync();

    // ===== Phase D: agg2 (+ reset g_cnt for next replay) ====================
    {
        const int l = tid & 7;
        const int gr0 = bid * (THREADS / 8) + (tid >> 3);
        const int grs = nb * (THREADS / 8);
        const float b2v = __ldg(&b2[0]);
        for (int node = gr0; node < NN; node += grs) {
            const int deg = g_cnt[node];
            const int base = node * CAP;
            float acc = 0.f;
            for (int j = l; j < deg; j += 8)
                acc += __ldg(&g_q[__ldg(&g_buck[base + j])]);
            #pragma unroll
            for (int o = 4; o; o >>= 1)
                acc += __shfl_down_sync(0xffffffffu, acc, o, 8);
            if (l == 0) {
                float di = g_dinv[node];
                out[node] = b2v + di * (g_q[node] + acc);
                g_cnt[node] = 0;          // leave counters clean for next replay
            }
        }
    }
}

// ---------------- launch ---------------------------------------------------
extern "C" void kernel_launch(void* const* d_in, const int* in_sizes, int n_in,
                              void* d_out, int out_size) {
    const float* x  = (const float*)d_in[0];
    const int*   ei = (const int*)d_in[1];
    const float* W1 = (const float*)d_in[2];
    const float* b1 = (const float*)d_in[3];
    const float* W2 = (const float*)d_in[4];
    const float* b2 = (const float*)d_in[5];
    float*       out = (float*)d_out;

    const int4* src4 = (const int4*)(ei);        // edge_index[0]
    const int4* dst4 = (const int4*)(ei + EE);   // edge_index[1]

    // grid = 6 blocks/SM; __launch_bounds__(256,6) + 16KB smem/block give
    // ample co-residency margin, so the software grid barrier cannot deadlock.
    static int nblocks = 0;
    if (!nblocks) {
        int sms = 0;
        cudaDeviceGetAttribute(&sms, cudaDevAttrMultiProcessorCount, 0);
        nblocks = 6 * (sms > 0 ? sms : 148);
    }

    k_fused<<<nblocks, THREADS>>>(x, src4, dst4, W1, b1, W2, b2, out);
}

// round 13
// speedup vs baseline: 1.8858x; 1.8858x over previous
#include <cuda_runtime.h>
#include <cuda_bf16.h>
#include <math.h>

#define NN 50000
#define EE 800000
#define DD 64
#define CAP 64               // bucket capacity per node (deg~Pois(16); P(>=64)~1e-20)
#define GM_NODES 64          // nodes per gemm block

// ---------------- scratch (device globals; no allocation allowed) ----------
__device__ int   g_cnt[NN];
__device__ __align__(16) int g_buck[NN * CAP];  // src indices, bucketed by dst
__device__ float g_dinv[NN];
__device__ __align__(16) float g_h0[NN * DD];   // x @ W1 (unscaled)
__device__ float g_q[NN];                       // dinv * (relu(.)@W2)

// ---------------- kernels --------------------------------------------------

// Fused count + place: one pass over edges, bucket by destination.
__global__ void k_countplace(const int4* __restrict__ src4,
                             const int4* __restrict__ dst4) {
    int i = blockIdx.x * blockDim.x + threadIdx.x;
    if (i < EE / 4) {
        int4 s = src4[i];
        int4 d = dst4[i];
        g_buck[d.x * CAP + atomicAdd(&g_cnt[d.x], 1)] = s.x;
        g_buck[d.y * CAP + atomicAdd(&g_cnt[d.y], 1)] = s.y;
        g_buck[d.z * CAP + atomicAdd(&g_cnt[d.z], 1)] = s.z;
        g_buck[d.w * CAP + atomicAdd(&g_cnt[d.w], 1)] = s.w;
    }
}

__global__ void k_dinv() {
    int i = blockIdx.x * blockDim.x + threadIdx.x;
    if (i < NN) g_dinv[i] = rsqrtf((float)(g_cnt[i] + 1));   // +1 self-loop
}

// h0 = x @ W1 (unscaled; fully independent of the edge pipeline).
__global__ void k_gemm1(const float* __restrict__ x,
                        const float* __restrict__ W1) {
    __shared__ float sW[DD * DD];          // 16 KB
    __shared__ float sx[GM_NODES * 65];    // padded (bank-conflict-free)
    const int t = threadIdx.x;
    const int node0 = blockIdx.x * GM_NODES;

    for (int j = t; j < DD * DD / 4; j += 256)
        ((float4*)sW)[j] = ((const float4*)W1)[j];

    for (int j = t; j < GM_NODES * DD / 4; j += 256) {
        int idx = j * 4;
        int n = idx >> 6;
        int k = idx & 63;
        float4 v = make_float4(0.f, 0.f, 0.f, 0.f);
        if (node0 + n < NN)
            v = ((const float4*)(x + (size_t)(node0 + n) * DD))[k >> 2];
        sx[n * 65 + k]     = v.x;
        sx[n * 65 + k + 1] = v.y;
        sx[n * 65 + k + 2] = v.z;
        sx[n * 65 + k + 3] = v.w;
    }
    __syncthreads();

    const int dg = t & 7;    // 8 dim-groups of 8
    const int ng = t >> 3;   // 32 node-groups of 2
    float acc[2][8];
    #pragma unroll
    for (int i = 0; i < 2; i++)
        #pragma unroll
        for (int j = 0; j < 8; j++) acc[i][j] = 0.f;

    #pragma unroll 4
    for (int k = 0; k < DD; k++) {
        float4 wa = *(const float4*)&sW[k * DD + dg * 8];
        float4 wb = *(const float4*)&sW[k * DD + dg * 8 + 4];
        #pragma unroll
        for (int i = 0; i < 2; i++) {
            float xv = sx[(ng * 2 + i) * 65 + k];
            acc[i][0] = fmaf(xv, wa.x, acc[i][0]);
            acc[i][1] = fmaf(xv, wa.y, acc[i][1]);
            acc[i][2] = fmaf(xv, wa.z, acc[i][2]);
            acc[i][3] = fmaf(xv, wa.w, acc[i][3]);
            acc[i][4] = fmaf(xv, wb.x, acc[i][4]);
            acc[i][5] = fmaf(xv, wb.y, acc[i][5]);
            acc[i][6] = fmaf(xv, wb.z, acc[i][6]);
            acc[i][7] = fmaf(xv, wb.w, acc[i][7]);
        }
    }
    #pragma unroll
    for (int i = 0; i < 2; i++) {
        int node = node0 + ng * 2 + i;
        if (node < NN) {
            float* dstp = g_h0 + (size_t)node * DD + dg * 8;
            *(float4*)dstp       = make_float4(acc[i][0], acc[i][1], acc[i][2], acc[i][3]);
            *(float4*)(dstp + 4) = make_float4(acc[i][4], acc[i][5], acc[i][6], acc[i][7]);
        }
    }
}

// Fused agg1 + bias + relu + W2 projection -> q = dinv * p.  Half-warp/node.
// Proven config: 4-edge unroll, scalar index loads, occ ~81%.
__global__ void k_agg1(const float* __restrict__ b1,
                       const float* __restrict__ W2) {
    const int node = (blockIdx.x * blockDim.x + threadIdx.x) >> 4;
    if (node >= NN) return;
    const int l = threadIdx.x & 15;

    const float di  = g_dinv[node];
    const int   deg = g_cnt[node];
    const int   base = node * CAP;

    float4 v0 = ((const float4*)(g_h0 + (size_t)node * DD))[l];   // self
    float ax = di * v0.x, ay = di * v0.y, az = di * v0.z, aw = di * v0.w;

    int j = 0;
    for (; j + 4 <= deg; j += 4) {
        int c0 = __ldg(&g_buck[base + j]);
        int c1 = __ldg(&g_buck[base + j + 1]);
        int c2 = __ldg(&g_buck[base + j + 2]);
        int c3 = __ldg(&g_buck[base + j + 3]);
        float w0 = __ldg(&g_dinv[c0]);
        float w1 = __ldg(&g_dinv[c1]);
        float w2 = __ldg(&g_dinv[c2]);
        float w3 = __ldg(&g_dinv[c3]);
        float4 a = ((const float4*)(g_h0 + (size_t)c0 * DD))[l];
        float4 b = ((const float4*)(g_h0 + (size_t)c1 * DD))[l];
        float4 c = ((const float4*)(g_h0 + (size_t)c2 * DD))[l];
        float4 d = ((const float4*)(g_h0 + (size_t)c3 * DD))[l];
        ax = fmaf(w0, a.x, fmaf(w1, b.x, fmaf(w2, c.x, fmaf(w3, d.x, ax))));
        ay = fmaf(w0, a.y, fmaf(w1, b.y, fmaf(w2, c.y, fmaf(w3, d.y, ay))));
        az = fmaf(w0, a.z, fmaf(w1, b.z, fmaf(w2, c.z, fmaf(w3, d.z, az))));
        aw = fmaf(w0, a.w, fmaf(w1, b.w, fmaf(w2, c.w, fmaf(w3, d.w, aw))));
    }
    for (; j < deg; j++) {
        int c0 = __ldg(&g_buck[base + j]);
        float w0 = __ldg(&g_dinv[c0]);
        float4 a = ((const float4*)(g_h0 + (size_t)c0 * DD))[l];
        ax = fmaf(w0, a.x, ax); ay = fmaf(w0, a.y, ay);
        az = fmaf(w0, a.z, az); aw = fmaf(w0, a.w, aw);
    }

    float4 bb = ((const float4*)b1)[l];
    float4 ww = ((const float4*)W2)[l];
    float part = fmaxf(ax * di + bb.x, 0.f) * ww.x
               + fmaxf(ay * di + bb.y, 0.f) * ww.y
               + fmaxf(az * di + bb.z, 0.f) * ww.z
               + fmaxf(aw * di + bb.w, 0.f) * ww.w;
    #pragma unroll
    for (int o = 8; o; o >>= 1) part += __shfl_down_sync(0xffffffffu, part, o, 16);
    if (l == 0) g_q[node] = di * part;
}

// Layer-2: out = b2 + dinv*(q[node] + sum q[src]).  8 lanes per node.
__global__ void k_agg2(const float* __restrict__ b2,
                       float* __restrict__ out) {
    const int node = (blockIdx.x * blockDim.x + threadIdx.x) >> 3;
    if (node >= NN) return;
    const int l = threadIdx.x & 7;

    const int deg = g_cnt[node];
    const int base = node * CAP;
    float acc = 0.f;
    for (int j = l; j < deg; j += 8)
        acc += __ldg(&g_q[__ldg(&g_buck[base + j])]);
    #pragma unroll
    for (int o = 4; o; o >>= 1) acc += __shfl_down_sync(0xffffffffu, acc, o, 8);
    if (l == 0) {
        float di = g_dinv[node];
        out[node] = __ldg(&b2[0]) + di * (g_q[node] + acc);
    }
}

// ---------------- launch ---------------------------------------------------
extern "C" void kernel_launch(void* const* d_in, const int* in_sizes, int n_in,
                              void* d_out, int out_size) {
    const float* x  = (const float*)d_in[0];
    const int*   ei = (const int*)d_in[1];
    const float* W1 = (const float*)d_in[2];
    const float* b1 = (const float*)d_in[3];
    const float* W2 = (const float*)d_in[4];
    const float* b2 = (const float*)d_in[5];
    float*       out = (float*)d_out;

    const int4* src4 = (const int4*)(ei);        // edge_index[0]
    const int4* dst4 = (const int4*)(ei + EE);   // edge_index[1]

    // Lazily-created side stream + events (host objects cached; identical
    // device work every call).
    static cudaStream_t s2 = nullptr;
    static cudaEvent_t  e1 = nullptr, e2 = nullptr;
    if (!s2) {
        cudaStreamCreateWithFlags(&s2, cudaStreamNonBlocking);
        cudaEventCreateWithFlags(&e1, cudaEventDisableTiming);
        cudaEventCreateWithFlags(&e2, cudaEventDisableTiming);
    }

    // enqueue the cnt clear first (it gates countplace on stream 0)
    void* cnt_ptr = nullptr;
    cudaGetSymbolAddress(&cnt_ptr, g_cnt);
    cudaMemsetAsync(cnt_ptr, 0, NN * sizeof(int));

    // fork: gemm is fully independent of the edge pipeline
    cudaEventRecord(e1, 0);
    cudaStreamWaitEvent(s2, e1, 0);
    k_gemm1<<<(NN + GM_NODES - 1) / GM_NODES, 256, 0, s2>>>(x, W1);
    cudaEventRecord(e2, s2);

    k_countplace<<<(EE / 4 + 255) / 256, 256>>>(src4, dst4);
    k_dinv      <<<(NN + 255) / 256, 256>>>();

    // join gemm before aggregation
    cudaStreamWaitEvent(0, e2, 0);
    k_agg1<<<(NN * 16 + 255) / 256, 256>>>(b1, W2);
    k_agg2<<<(NN * 8 + 255) / 256, 256>>>(b2, out);
}